// round 1
// baseline (speedup 1.0000x reference)
#include <cuda_runtime.h>
#include <cuda_bf16.h>
#include <math.h>

// Problem dims
#define BSZ 4
#define SEQ 4096
#define DM  512
#define NROWS (BSZ * SEQ)   // 16384

// SGEMM tiling
#define BM 128
#define BN 128
#define BKD 16
#define TM 8
#define TN 8
#define NTHREADS 256

#define SOFTMAX_SCALE 0.04419417382415922f  // 1/sqrt(512)

// Scratch for Q, K, V projections (32 MB each)
__device__ float g_Q[NROWS * DM];
__device__ float g_K[NROWS * DM];
__device__ float g_V[NROWS * DM];

// ---------------------------------------------------------------------------
// Kernel 1: QKV projection.  C = X[16384,512] @ W^T  (NT gemm, W is [512,512]
// row-major with K contiguous).  grid.z selects which of Q/K/V.
// ---------------------------------------------------------------------------
__global__ __launch_bounds__(NTHREADS)
void qkv_kernel(const float* __restrict__ x,
                const float* __restrict__ WQ,
                const float* __restrict__ WK,
                const float* __restrict__ WV)
{
    const int which = blockIdx.z;
    const float* __restrict__ W = (which == 0) ? WQ : (which == 1) ? WK : WV;
    float* __restrict__ C = (which == 0) ? g_Q : (which == 1) ? g_K : g_V;

    const int m0 = blockIdx.y * BM;
    const int n0 = blockIdx.x * BN;

    __shared__ float As[BKD][BM];
    __shared__ float Bs[BKD][BN];

    const int t  = threadIdx.x;
    const int tx = t & 15;        // 0..15 -> N direction
    const int ty = t >> 4;        // 0..15 -> M direction

    float acc[TM][TN];
    #pragma unroll
    for (int a = 0; a < TM; a++)
        #pragma unroll
        for (int b = 0; b < TN; b++) acc[a][b] = 0.0f;

    for (int k0 = 0; k0 < DM; k0 += BKD) {
        // Load A tile (128x16) transposed into As
        #pragma unroll
        for (int i = 0; i < 2; i++) {
            int idx = t + i * NTHREADS;          // 0..511 float4 slots
            int row = idx >> 2;
            int c4  = idx & 3;
            float4 v = *reinterpret_cast<const float4*>(
                &x[(size_t)(m0 + row) * DM + k0 + c4 * 4]);
            As[c4 * 4 + 0][row] = v.x;
            As[c4 * 4 + 1][row] = v.y;
            As[c4 * 4 + 2][row] = v.z;
            As[c4 * 4 + 3][row] = v.w;
        }
        // Load B tile (W rows n0..n0+127, cols k0..k0+15) transposed into Bs
        #pragma unroll
        for (int i = 0; i < 2; i++) {
            int idx = t + i * NTHREADS;
            int row = idx >> 2;
            int c4  = idx & 3;
            float4 v = *reinterpret_cast<const float4*>(
                &W[(size_t)(n0 + row) * DM + k0 + c4 * 4]);
            Bs[c4 * 4 + 0][row] = v.x;
            Bs[c4 * 4 + 1][row] = v.y;
            Bs[c4 * 4 + 2][row] = v.z;
            Bs[c4 * 4 + 3][row] = v.w;
        }
        __syncthreads();

        #pragma unroll
        for (int kk = 0; kk < BKD; kk++) {
            float ra[TM], rb[TN];
            #pragma unroll
            for (int a = 0; a < TM; a++) ra[a] = As[kk][ty * TM + a];
            #pragma unroll
            for (int b = 0; b < TN; b++) rb[b] = Bs[kk][tx * TN + b];
            #pragma unroll
            for (int a = 0; a < TM; a++)
                #pragma unroll
                for (int b = 0; b < TN; b++)
                    acc[a][b] += ra[a] * rb[b];
        }
        __syncthreads();
    }

    #pragma unroll
    for (int a = 0; a < TM; a++) {
        int row = m0 + ty * TM + a;
        float* dst = &C[(size_t)row * DM + n0 + tx * TN];
        float4 v0 = make_float4(acc[a][0], acc[a][1], acc[a][2], acc[a][3]);
        float4 v1 = make_float4(acc[a][4], acc[a][5], acc[a][6], acc[a][7]);
        reinterpret_cast<float4*>(dst)[0] = v0;
        reinterpret_cast<float4*>(dst)[1] = v1;
    }
}

// ---------------------------------------------------------------------------
// Kernel 2: raw scores = scale * Q @ K^T per batch (NT gemm, causal tiles only).
// Writes raw scores into the attention output region (used as scratch).
// ---------------------------------------------------------------------------
__global__ __launch_bounds__(NTHREADS)
void scores_kernel(float* __restrict__ att)
{
    const int kt = blockIdx.x;
    const int qt = blockIdx.y;
    if (kt > qt) return;                 // strictly-upper tiles: all masked
    const int b = blockIdx.z;

    const float* __restrict__ Q = g_Q + (size_t)b * SEQ * DM;
    const float* __restrict__ K = g_K + (size_t)b * SEQ * DM;
    float* __restrict__ attb = att + (size_t)b * SEQ * SEQ;

    const int m0 = qt * BM;              // query rows
    const int n0 = kt * BN;              // key cols

    __shared__ float As[BKD][BM];
    __shared__ float Bs[BKD][BN];

    const int t  = threadIdx.x;
    const int tx = t & 15;
    const int ty = t >> 4;

    float acc[TM][TN];
    #pragma unroll
    for (int a = 0; a < TM; a++)
        #pragma unroll
        for (int bb = 0; bb < TN; bb++) acc[a][bb] = 0.0f;

    for (int k0 = 0; k0 < DM; k0 += BKD) {
        #pragma unroll
        for (int i = 0; i < 2; i++) {
            int idx = t + i * NTHREADS;
            int row = idx >> 2;
            int c4  = idx & 3;
            float4 v = *reinterpret_cast<const float4*>(
                &Q[(size_t)(m0 + row) * DM + k0 + c4 * 4]);
            As[c4 * 4 + 0][row] = v.x;
            As[c4 * 4 + 1][row] = v.y;
            As[c4 * 4 + 2][row] = v.z;
            As[c4 * 4 + 3][row] = v.w;
        }
        #pragma unroll
        for (int i = 0; i < 2; i++) {
            int idx = t + i * NTHREADS;
            int row = idx >> 2;
            int c4  = idx & 3;
            float4 v = *reinterpret_cast<const float4*>(
                &K[(size_t)(n0 + row) * DM + k0 + c4 * 4]);
            Bs[c4 * 4 + 0][row] = v.x;
            Bs[c4 * 4 + 1][row] = v.y;
            Bs[c4 * 4 + 2][row] = v.z;
            Bs[c4 * 4 + 3][row] = v.w;
        }
        __syncthreads();

        #pragma unroll
        for (int kk = 0; kk < BKD; kk++) {
            float ra[TM], rb[TN];
            #pragma unroll
            for (int a = 0; a < TM; a++) ra[a] = As[kk][ty * TM + a];
            #pragma unroll
            for (int bb = 0; bb < TN; bb++) rb[bb] = Bs[kk][tx * TN + bb];
            #pragma unroll
            for (int a = 0; a < TM; a++)
                #pragma unroll
                for (int bb = 0; bb < TN; bb++)
                    acc[a][bb] += ra[a] * rb[bb];
        }
        __syncthreads();
    }

    #pragma unroll
    for (int a = 0; a < TM; a++) {
        int row = m0 + ty * TM + a;
        float* dst = &attb[(size_t)row * SEQ + n0 + tx * TN];
        float4 v0 = make_float4(acc[a][0] * SOFTMAX_SCALE, acc[a][1] * SOFTMAX_SCALE,
                                acc[a][2] * SOFTMAX_SCALE, acc[a][3] * SOFTMAX_SCALE);
        float4 v1 = make_float4(acc[a][4] * SOFTMAX_SCALE, acc[a][5] * SOFTMAX_SCALE,
                                acc[a][6] * SOFTMAX_SCALE, acc[a][7] * SOFTMAX_SCALE);
        reinterpret_cast<float4*>(dst)[0] = v0;
        reinterpret_cast<float4*>(dst)[1] = v1;
    }
}

// ---------------------------------------------------------------------------
// Kernel 3: exact row softmax in place; zeros the masked (upper-tri) region.
// One block per row; full row (<=16KB) staged in shared memory.
// ---------------------------------------------------------------------------
__global__ __launch_bounds__(NTHREADS)
void softmax_kernel(float* __restrict__ att)
{
    const int r = blockIdx.x;            // 0..16383
    const int b = r >> 12;
    const int q = r & (SEQ - 1);
    float* __restrict__ row = att + (size_t)b * SEQ * SEQ + (size_t)q * SEQ;
    const int L = q + 1;                 // valid (causal) length

    __shared__ float sm[SEQ];
    __shared__ float red[NTHREADS];

    const int t = threadIdx.x;

    float mx = -INFINITY;
    for (int j = t; j < L; j += NTHREADS) {
        float v = row[j];
        sm[j] = v;
        mx = fmaxf(mx, v);
    }
    red[t] = mx;
    __syncthreads();
    #pragma unroll
    for (int s = NTHREADS / 2; s > 0; s >>= 1) {
        if (t < s) red[t] = fmaxf(red[t], red[t + s]);
        __syncthreads();
    }
    const float rowmax = red[0];
    __syncthreads();

    float sum = 0.0f;
    for (int j = t; j < L; j += NTHREADS) {
        float e = __expf(sm[j] - rowmax);
        sm[j] = e;
        sum += e;
    }
    red[t] = sum;
    __syncthreads();
    #pragma unroll
    for (int s = NTHREADS / 2; s > 0; s >>= 1) {
        if (t < s) red[t] += red[t + s];
        __syncthreads();
    }
    const float inv = 1.0f / red[0];

    for (int j = t; j < SEQ; j += NTHREADS) {
        row[j] = (j < L) ? sm[j] * inv : 0.0f;
    }
}

// ---------------------------------------------------------------------------
// Kernel 4: O = P @ V + x  (NN gemm per batch; K-loop truncated at the
// causal diagonal band since P is zero beyond it).
// ---------------------------------------------------------------------------
__global__ __launch_bounds__(NTHREADS)
void av_kernel(const float* __restrict__ x,
               const float* __restrict__ att,
               float* __restrict__ out)
{
    const int b  = blockIdx.z;
    const int qt = blockIdx.y;
    const int m0 = qt * BM;
    const int n0 = blockIdx.x * BN;

    const float* __restrict__ P = att + (size_t)b * SEQ * SEQ;
    const float* __restrict__ V = g_V + (size_t)b * SEQ * DM;

    __shared__ float As[BKD][BM];
    __shared__ float Bs[BKD][BN];

    const int t  = threadIdx.x;
    const int tx = t & 15;
    const int ty = t >> 4;

    float acc[TM][TN];
    #pragma unroll
    for (int a = 0; a < TM; a++)
        #pragma unroll
        for (int bb = 0; bb < TN; bb++) acc[a][bb] = 0.0f;

    const int kend = (qt + 1) * BM;      // only k <= q contributes

    for (int k0 = 0; k0 < kend; k0 += BKD) {
        // P tile 128x16, ld = SEQ, transposed into As
        #pragma unroll
        for (int i = 0; i < 2; i++) {
            int idx = t + i * NTHREADS;
            int row = idx >> 2;
            int c4  = idx & 3;
            float4 v = *reinterpret_cast<const float4*>(
                &P[(size_t)(m0 + row) * SEQ + k0 + c4 * 4]);
            As[c4 * 4 + 0][row] = v.x;
            As[c4 * 4 + 1][row] = v.y;
            As[c4 * 4 + 2][row] = v.z;
            As[c4 * 4 + 3][row] = v.w;
        }
        // V tile 16x128, ld = DM, natural layout in Bs
        #pragma unroll
        for (int i = 0; i < 2; i++) {
            int idx = t + i * NTHREADS;  // 0..511 float4 slots
            int row = idx >> 5;          // 0..15
            int c4  = idx & 31;          // 0..31 float4 cols
            float4 v = *reinterpret_cast<const float4*>(
                &V[(size_t)(k0 + row) * DM + n0 + c4 * 4]);
            Bs[row][c4 * 4 + 0] = v.x;
            Bs[row][c4 * 4 + 1] = v.y;
            Bs[row][c4 * 4 + 2] = v.z;
            Bs[row][c4 * 4 + 3] = v.w;
        }
        __syncthreads();

        #pragma unroll
        for (int kk = 0; kk < BKD; kk++) {
            float ra[TM], rb[TN];
            #pragma unroll
            for (int a = 0; a < TM; a++) ra[a] = As[kk][ty * TM + a];
            #pragma unroll
            for (int bb = 0; bb < TN; bb++) rb[bb] = Bs[kk][tx * TN + bb];
            #pragma unroll
            for (int a = 0; a < TM; a++)
                #pragma unroll
                for (int bb = 0; bb < TN; bb++)
                    acc[a][bb] += ra[a] * rb[bb];
        }
        __syncthreads();
    }

    #pragma unroll
    for (int a = 0; a < TM; a++) {
        int row = m0 + ty * TM + a;
        size_t base = ((size_t)b * SEQ + row) * DM + n0 + tx * TN;
        float4 xv0 = reinterpret_cast<const float4*>(&x[base])[0];
        float4 xv1 = reinterpret_cast<const float4*>(&x[base])[1];
        float4 v0 = make_float4(acc[a][0] + xv0.x, acc[a][1] + xv0.y,
                                acc[a][2] + xv0.z, acc[a][3] + xv0.w);
        float4 v1 = make_float4(acc[a][4] + xv1.x, acc[a][5] + xv1.y,
                                acc[a][6] + xv1.z, acc[a][7] + xv1.w);
        reinterpret_cast<float4*>(&out[base])[0] = v0;
        reinterpret_cast<float4*>(&out[base])[1] = v1;
    }
}

// ---------------------------------------------------------------------------
extern "C" void kernel_launch(void* const* d_in, const int* in_sizes, int n_in,
                              void* d_out, int out_size)
{
    const float* x  = (const float*)d_in[0];
    const float* WQ = (const float*)d_in[1];
    const float* WK = (const float*)d_in[2];
    const float* WV = (const float*)d_in[3];

    float* out = (float*)d_out;                        // [B,S,D]
    float* att = out + (size_t)BSZ * SEQ * DM;         // [B,S,S]

    // 1) QKV projections
    dim3 g1(DM / BN, NROWS / BM, 3);
    qkv_kernel<<<g1, NTHREADS>>>(x, WQ, WK, WV);

    // 2) raw causal scores into attention region
    dim3 g2(SEQ / BN, SEQ / BM, BSZ);
    scores_kernel<<<g2, NTHREADS>>>(att);

    // 3) exact softmax per row (+ zero upper triangle)
    softmax_kernel<<<NROWS, NTHREADS>>>(att);

    // 4) O = P @ V + x
    dim3 g4(DM / BN, SEQ / BM, BSZ);
    av_kernel<<<g4, NTHREADS>>>(x, att, out);
}

// round 3
// speedup vs baseline: 2.6484x; 2.6484x over previous
#include <cuda_runtime.h>
#include <cuda_bf16.h>
#include <math.h>
#include <stdint.h>

// ---------------------------------------------------------------- dims
#define BSZ 4
#define SEQ 4096
#define DM  512
#define NROWS (BSZ * SEQ)                 // 16384
#define NTH 256
#define BM 128
#define BN 128
#define BK 32
#define SOFTMAX_SCALE 0.04419417382415922f

// smem stage layout (bf16 tiles, 64-byte rows, SW64 swizzle)
#define SA_H 0
#define SA_L 8192
#define SB_H 16384
#define SB_L 24576
#define STAGE 32768
#define SMEM_TOTAL (2 * STAGE)            // 64 KB

#define SW64(o) ((uint32_t)(o) ^ ((((uint32_t)(o)) >> 3) & 0x30u))

// ---------------------------------------------------------------- scratch
__device__ __nv_bfloat16 g_xh[(size_t)NROWS * DM];
__device__ __nv_bfloat16 g_xl[(size_t)NROWS * DM];
__device__ __nv_bfloat16 g_Wh[3 * DM * DM];
__device__ __nv_bfloat16 g_Wl[3 * DM * DM];
__device__ __nv_bfloat16 g_Qh[(size_t)NROWS * DM];   // pre-scaled by 1/sqrt(D)
__device__ __nv_bfloat16 g_Ql[(size_t)NROWS * DM];
__device__ __nv_bfloat16 g_Kh[(size_t)NROWS * DM];
__device__ __nv_bfloat16 g_Kl[(size_t)NROWS * DM];
__device__ __nv_bfloat16 g_Vth[(size_t)BSZ * DM * SEQ];  // V^T [b][d][s]
__device__ __nv_bfloat16 g_Vtl[(size_t)BSZ * DM * SEQ];
__device__ __nv_bfloat16 g_Ph[(size_t)BSZ * SEQ * SEQ];  // probs hi/lo
__device__ __nv_bfloat16 g_Pl[(size_t)BSZ * SEQ * SEQ];

// ---------------------------------------------------------------- helpers
__device__ __forceinline__ uint32_t smem_u32(const void* p) {
    return (uint32_t)__cvta_generic_to_shared(p);
}
__device__ __forceinline__ void ldmx4(uint32_t r[4], uint32_t addr) {
    asm volatile("ldmatrix.sync.aligned.m8n8.x4.shared.b16 {%0,%1,%2,%3}, [%4];"
                 : "=r"(r[0]), "=r"(r[1]), "=r"(r[2]), "=r"(r[3]) : "r"(addr));
}
__device__ __forceinline__ void mma16816(float d[4], const uint32_t a[4],
                                         uint32_t b0, uint32_t b1) {
    asm volatile("mma.sync.aligned.m16n8k16.row.col.f32.bf16.bf16.f32 "
                 "{%0,%1,%2,%3}, {%4,%5,%6,%7}, {%8,%9}, {%0,%1,%2,%3};"
                 : "+f"(d[0]), "+f"(d[1]), "+f"(d[2]), "+f"(d[3])
                 : "r"(a[0]), "r"(a[1]), "r"(a[2]), "r"(a[3]), "r"(b0), "r"(b1));
}
__device__ __forceinline__ void cpasync16(uint32_t dst, const void* src) {
    asm volatile("cp.async.cg.shared.global [%0], [%1], 16;" :: "r"(dst), "l"(src));
}
#define CP_COMMIT() asm volatile("cp.async.commit_group;")
#define CP_WAIT(N)  asm volatile("cp.async.wait_group %0;" :: "n"(N))

__device__ __forceinline__ void split_bf16(float v, uint16_t& h, uint16_t& l) {
    __nv_bfloat16 hb = __float2bfloat16(v);
    float r = v - __bfloat162float(hb);
    h = __bfloat16_as_ushort(hb);
    l = __bfloat16_as_ushort(__float2bfloat16(r));
}

// load one 128x32 bf16 tile into swizzled smem via cp.async (2x16B per thread)
__device__ __forceinline__ void load_tile(uint32_t sdst, const __nv_bfloat16* g,
                                          size_t ld, int t) {
    #pragma unroll
    for (int j = 0; j < 2; j++) {
        int i = t + j * NTH;            // 0..511
        int row = i >> 2, c = i & 3;
        cpasync16(sdst + SW64((row << 6) + (c << 4)), g + (size_t)row * ld + c * 8);
    }
}
__device__ __forceinline__ void load_chunk(uint32_t s,
                                           const __nv_bfloat16* Ah, const __nv_bfloat16* Al,
                                           const __nv_bfloat16* Bh, const __nv_bfloat16* Bl,
                                           size_t ldA, size_t ldB, int k0, int t) {
    load_tile(s + SA_H, Ah + k0, ldA, t);
    load_tile(s + SA_L, Al + k0, ldA, t);
    load_tile(s + SB_H, Bh + k0, ldB, t);
    load_tile(s + SB_L, Bl + k0, ldB, t);
}

// compute one BK=32 chunk: acc += Ah*Bh + Ah*Bl + Al*Bh (warp tile 32x64)
__device__ __forceinline__ void compute_stage(uint32_t s, int wr, int wc, int lane,
                                              float acc[2][8][4]) {
    #pragma unroll
    for (int ks = 0; ks < 2; ks++) {
        const int k0 = ks * 16;
        uint32_t ah[2][4], al[2][4];
        const int arow = wr * 32 + (lane & 15);
        const int acol = k0 + ((lane >> 4) << 3);
        #pragma unroll
        for (int mi = 0; mi < 2; mi++) {
            uint32_t off = SW64(((arow + mi * 16) << 6) + (acol << 1));
            ldmx4(ah[mi], s + SA_H + off);
            ldmx4(al[mi], s + SA_L + off);
        }
        const int brow = wc * 64 + ((lane >> 4) << 3) + (lane & 7);
        const int bcol = k0 + (((lane >> 3) & 1) << 3);
        #pragma unroll
        for (int p = 0; p < 4; p++) {
            uint32_t bh[4], bl[4];
            uint32_t off = SW64(((brow + p * 16) << 6) + (bcol << 1));
            ldmx4(bh, s + SB_H + off);
            ldmx4(bl, s + SB_L + off);
            #pragma unroll
            for (int mi = 0; mi < 2; mi++) {
                mma16816(acc[mi][2 * p],     ah[mi], bh[0], bh[1]);
                mma16816(acc[mi][2 * p + 1], ah[mi], bh[2], bh[3]);
                mma16816(acc[mi][2 * p],     ah[mi], bl[0], bl[1]);
                mma16816(acc[mi][2 * p + 1], ah[mi], bl[2], bl[3]);
                mma16816(acc[mi][2 * p],     al[mi], bh[0], bh[1]);
                mma16816(acc[mi][2 * p + 1], al[mi], bh[2], bh[3]);
            }
        }
    }
}

#define GEMM_PIPELINE(Ah, Al, Bh, Bl, ldA, ldB, nch)                              \
    do {                                                                          \
        load_chunk(sb, Ah, Al, Bh, Bl, ldA, ldB, 0, t);                           \
        CP_COMMIT();                                                              \
        for (int c = 0; c < (nch); c++) {                                         \
            if (c + 1 < (nch)) {                                                  \
                load_chunk(sb + ((c + 1) & 1) * STAGE, Ah, Al, Bh, Bl,            \
                           ldA, ldB, (c + 1) * BK, t);                            \
                CP_COMMIT();                                                      \
                CP_WAIT(1);                                                       \
            } else {                                                              \
                CP_WAIT(0);                                                       \
            }                                                                     \
            __syncthreads();                                                      \
            compute_stage(sb + (c & 1) * STAGE, wr, wc, lane, acc);               \
            __syncthreads();                                                      \
        }                                                                         \
    } while (0)

// ---------------------------------------------------------------- split kernel
__global__ __launch_bounds__(NTH)
void split_kernel(const float* __restrict__ src, __nv_bfloat16* __restrict__ h,
                  __nv_bfloat16* __restrict__ l, int n4) {
    int i = blockIdx.x * NTH + threadIdx.x;
    if (i >= n4) return;
    float4 v = reinterpret_cast<const float4*>(src)[i];
    uint16_t h0, h1, h2, h3, l0, l1, l2, l3;
    split_bf16(v.x, h0, l0); split_bf16(v.y, h1, l1);
    split_bf16(v.z, h2, l2); split_bf16(v.w, h3, l3);
    reinterpret_cast<uint2*>(h)[i] =
        make_uint2((uint32_t)h0 | ((uint32_t)h1 << 16), (uint32_t)h2 | ((uint32_t)h3 << 16));
    reinterpret_cast<uint2*>(l)[i] =
        make_uint2((uint32_t)l0 | ((uint32_t)l1 << 16), (uint32_t)l2 | ((uint32_t)l3 << 16));
}

// ---------------------------------------------------------------- kernel: QKV
__global__ __launch_bounds__(NTH, 1)
void qkv_kernel() {
    extern __shared__ __align__(128) char smem[];
    const uint32_t sb = smem_u32(smem);
    const int t = threadIdx.x, wid = t >> 5, lane = t & 31;
    const int wr = wid & 3, wc = wid >> 2;
    const int which = blockIdx.z;
    const int m0 = blockIdx.y * BM;      // global row (b*SEQ+s)
    const int n0 = blockIdx.x * BN;

    const __nv_bfloat16* Ah = g_xh + (size_t)m0 * DM;
    const __nv_bfloat16* Al = g_xl + (size_t)m0 * DM;
    const __nv_bfloat16* Bh = g_Wh + (size_t)which * DM * DM + (size_t)n0 * DM;
    const __nv_bfloat16* Bl = g_Wl + (size_t)which * DM * DM + (size_t)n0 * DM;

    float acc[2][8][4];
    #pragma unroll
    for (int a = 0; a < 2; a++)
        #pragma unroll
        for (int b = 0; b < 8; b++)
            #pragma unroll
            for (int r = 0; r < 4; r++) acc[a][b][r] = 0.0f;

    GEMM_PIPELINE(Ah, Al, Bh, Bl, DM, DM, DM / BK);

    if (which < 2) {
        __nv_bfloat16* Dh = (which == 0) ? g_Qh : g_Kh;
        __nv_bfloat16* Dl = (which == 0) ? g_Ql : g_Kl;
        const float sc = (which == 0) ? SOFTMAX_SCALE : 1.0f;
        #pragma unroll
        for (int mi = 0; mi < 2; mi++) {
            #pragma unroll
            for (int ni = 0; ni < 8; ni++) {
                int row = m0 + wr * 32 + mi * 16 + (lane >> 2);
                int col = n0 + wc * 64 + ni * 8 + ((lane & 3) << 1);
                uint16_t h0, h1, l0, l1;
                split_bf16(acc[mi][ni][0] * sc, h0, l0);
                split_bf16(acc[mi][ni][1] * sc, h1, l1);
                *reinterpret_cast<uint32_t*>(&Dh[(size_t)row * DM + col]) =
                    (uint32_t)h0 | ((uint32_t)h1 << 16);
                *reinterpret_cast<uint32_t*>(&Dl[(size_t)row * DM + col]) =
                    (uint32_t)l0 | ((uint32_t)l1 << 16);
                split_bf16(acc[mi][ni][2] * sc, h0, l0);
                split_bf16(acc[mi][ni][3] * sc, h1, l1);
                *reinterpret_cast<uint32_t*>(&Dh[(size_t)(row + 8) * DM + col]) =
                    (uint32_t)h0 | ((uint32_t)h1 << 16);
                *reinterpret_cast<uint32_t*>(&Dl[(size_t)(row + 8) * DM + col]) =
                    (uint32_t)l0 | ((uint32_t)l1 << 16);
            }
        }
    } else {
        // V: transpose through smem, write V^T hi/lo coalesced
        __syncthreads();
        #pragma unroll
        for (int mi = 0; mi < 2; mi++) {
            #pragma unroll
            for (int ni = 0; ni < 8; ni++) {
                #pragma unroll
                for (int r = 0; r < 4; r++) {
                    int srow = wr * 32 + mi * 16 + (lane >> 2) + ((r >> 1) << 3);
                    int dcol = wc * 64 + ni * 8 + ((lane & 3) << 1) + (r & 1);
                    uint16_t h, l;
                    split_bf16(acc[mi][ni][r], h, l);
                    *reinterpret_cast<uint16_t*>(smem + dcol * 256 + srow * 2) = h;
                    *reinterpret_cast<uint16_t*>(smem + 32768 + dcol * 256 + srow * 2) = l;
                }
            }
        }
        __syncthreads();
        const int b = m0 >> 12, s0 = m0 & (SEQ - 1);
        const int d = t >> 1, half = t & 1;
        const uint4* sh = reinterpret_cast<const uint4*>(smem + d * 256 + half * 128);
        const uint4* sl = reinterpret_cast<const uint4*>(smem + 32768 + d * 256 + half * 128);
        size_t o = ((size_t)b * DM + n0 + d) * SEQ + s0 + half * 64;
        uint4* dh = reinterpret_cast<uint4*>(g_Vth + o);
        uint4* dl = reinterpret_cast<uint4*>(g_Vtl + o);
        #pragma unroll
        for (int q = 0; q < 8; q++) { dh[q] = sh[q]; dl[q] = sl[q]; }
    }
}

// ---------------------------------------------------------------- kernel: scores
__global__ __launch_bounds__(NTH, 1)
void scores_kernel(float* __restrict__ att) {
    const int kt = blockIdx.x, qt = blockIdx.y;
    if (kt > qt) return;
    const int b = blockIdx.z;

    extern __shared__ __align__(128) char smem[];
    const uint32_t sb = smem_u32(smem);
    const int t = threadIdx.x, wid = t >> 5, lane = t & 31;
    const int wr = wid & 3, wc = wid >> 2;

    const size_t qr = ((size_t)b * SEQ + qt * BM) * DM;
    const size_t kr = ((size_t)b * SEQ + kt * BN) * DM;
    const __nv_bfloat16* Ah = g_Qh + qr;
    const __nv_bfloat16* Al = g_Ql + qr;
    const __nv_bfloat16* Bh = g_Kh + kr;
    const __nv_bfloat16* Bl = g_Kl + kr;

    float acc[2][8][4];
    #pragma unroll
    for (int a = 0; a < 2; a++)
        #pragma unroll
        for (int c = 0; c < 8; c++)
            #pragma unroll
            for (int r = 0; r < 4; r++) acc[a][c][r] = 0.0f;

    GEMM_PIPELINE(Ah, Al, Bh, Bl, DM, DM, DM / BK);

    float* attb = att + (size_t)b * SEQ * SEQ;
    #pragma unroll
    for (int mi = 0; mi < 2; mi++) {
        #pragma unroll
        for (int ni = 0; ni < 8; ni++) {
            int row = qt * BM + wr * 32 + mi * 16 + (lane >> 2);
            int col = kt * BN + wc * 64 + ni * 8 + ((lane & 3) << 1);
            *reinterpret_cast<float2*>(&attb[(size_t)row * SEQ + col]) =
                make_float2(acc[mi][ni][0], acc[mi][ni][1]);
            *reinterpret_cast<float2*>(&attb[(size_t)(row + 8) * SEQ + col]) =
                make_float2(acc[mi][ni][2], acc[mi][ni][3]);
        }
    }
}

// ---------------------------------------------------------------- kernel: softmax
__global__ __launch_bounds__(NTH)
void softmax_kernel(float* __restrict__ att) {
    const int rr = blockIdx.x;
    const int b = rr >> 12;
    const int q = rr & (SEQ - 1);
    float* __restrict__ row = att + (size_t)b * SEQ * SEQ + (size_t)q * SEQ;
    __nv_bfloat16* __restrict__ ph = g_Ph + (size_t)b * SEQ * SEQ + (size_t)q * SEQ;
    __nv_bfloat16* __restrict__ pl = g_Pl + (size_t)b * SEQ * SEQ + (size_t)q * SEQ;
    const int L = q + 1;
    const int jmax = ((q >> 7) + 1) << 7;   // pad to 128 for the AV gemm

    __shared__ float sm[SEQ];
    __shared__ float red[NTH];
    const int t = threadIdx.x;

    float mx = -INFINITY;
    for (int j = t; j < L; j += NTH) {
        float v = row[j];
        sm[j] = v;
        mx = fmaxf(mx, v);
    }
    red[t] = mx;
    __syncthreads();
    #pragma unroll
    for (int s = NTH / 2; s > 0; s >>= 1) {
        if (t < s) red[t] = fmaxf(red[t], red[t + s]);
        __syncthreads();
    }
    const float rowmax = red[0];
    __syncthreads();

    float sum = 0.0f;
    for (int j = t; j < L; j += NTH) {
        float e = __expf(sm[j] - rowmax);
        sm[j] = e;
        sum += e;
    }
    red[t] = sum;
    __syncthreads();
    #pragma unroll
    for (int s = NTH / 2; s > 0; s >>= 1) {
        if (t < s) red[t] += red[t + s];
        __syncthreads();
    }
    const float inv = 1.0f / red[0];

    for (int j = t; j < SEQ; j += NTH) {
        float v = (j < L) ? sm[j] * inv : 0.0f;
        row[j] = v;
        if (j < jmax) {
            uint16_t h, l;
            split_bf16(v, h, l);
            ph[j] = __ushort_as_bfloat16(h);
            pl[j] = __ushort_as_bfloat16(l);
        }
    }
}

// ---------------------------------------------------------------- kernel: AV + residual
__global__ __launch_bounds__(NTH, 1)
void av_kernel(const float* __restrict__ x, float* __restrict__ out) {
    const int b = blockIdx.z;
    const int qt = blockIdx.y;
    const int n0 = blockIdx.x * BN;
    const int m0 = qt * BM;              // batch-local q row

    extern __shared__ __align__(128) char smem[];
    const uint32_t sb = smem_u32(smem);
    const int t = threadIdx.x, wid = t >> 5, lane = t & 31;
    const int wr = wid & 3, wc = wid >> 2;

    const size_t pr = ((size_t)b * SEQ + m0) * SEQ;
    const size_t vr = ((size_t)b * DM + n0) * SEQ;
    const __nv_bfloat16* Ah = g_Ph + pr;
    const __nv_bfloat16* Al = g_Pl + pr;
    const __nv_bfloat16* Bh = g_Vth + vr;
    const __nv_bfloat16* Bl = g_Vtl + vr;

    float acc[2][8][4];
    #pragma unroll
    for (int a = 0; a < 2; a++)
        #pragma unroll
        for (int c = 0; c < 8; c++)
            #pragma unroll
            for (int r = 0; r < 4; r++) acc[a][c][r] = 0.0f;

    const int nch = ((qt + 1) * BM) / BK;   // causal truncation

    GEMM_PIPELINE(Ah, Al, Bh, Bl, SEQ, SEQ, nch);

    #pragma unroll
    for (int mi = 0; mi < 2; mi++) {
        #pragma unroll
        for (int ni = 0; ni < 8; ni++) {
            int row = m0 + wr * 32 + mi * 16 + (lane >> 2);
            int col = n0 + wc * 64 + ni * 8 + ((lane & 3) << 1);
            size_t base = ((size_t)b * SEQ + row) * DM + col;
            float2 xv = *reinterpret_cast<const float2*>(&x[base]);
            *reinterpret_cast<float2*>(&out[base]) =
                make_float2(acc[mi][ni][0] + xv.x, acc[mi][ni][1] + xv.y);
            size_t base8 = base + (size_t)8 * DM;
            float2 xv8 = *reinterpret_cast<const float2*>(&x[base8]);
            *reinterpret_cast<float2*>(&out[base8]) =
                make_float2(acc[mi][ni][2] + xv8.x, acc[mi][ni][3] + xv8.y);
        }
    }
}

// ---------------------------------------------------------------- launch
extern "C" void kernel_launch(void* const* d_in, const int* in_sizes, int n_in,
                              void* d_out, int out_size) {
    const float* x  = (const float*)d_in[0];
    const float* WQ = (const float*)d_in[1];
    const float* WK = (const float*)d_in[2];
    const float* WV = (const float*)d_in[3];

    float* out = (float*)d_out;                   // [B,S,D]
    float* att = out + (size_t)BSZ * SEQ * DM;    // [B,S,S]

    static int configured = 0;
    if (!configured) {
        cudaFuncSetAttribute(qkv_kernel,    cudaFuncAttributeMaxDynamicSharedMemorySize, SMEM_TOTAL);
        cudaFuncSetAttribute(scores_kernel, cudaFuncAttributeMaxDynamicSharedMemorySize, SMEM_TOTAL);
        cudaFuncSetAttribute(av_kernel,     cudaFuncAttributeMaxDynamicSharedMemorySize, SMEM_TOTAL);
        configured = 1;
    }

    __nv_bfloat16 *xh, *xl, *Wh, *Wl;
    cudaGetSymbolAddress((void**)&xh, g_xh);
    cudaGetSymbolAddress((void**)&xl, g_xl);
    cudaGetSymbolAddress((void**)&Wh, g_Wh);
    cudaGetSymbolAddress((void**)&Wl, g_Wl);

    // 0) split fp32 inputs into bf16 hi/lo
    split_kernel<<<(NROWS * DM / 4 + NTH - 1) / NTH, NTH>>>(x, xh, xl, NROWS * DM / 4);
    split_kernel<<<(DM * DM / 4 + NTH - 1) / NTH, NTH>>>(WQ, Wh, Wl, DM * DM / 4);
    split_kernel<<<(DM * DM / 4 + NTH - 1) / NTH, NTH>>>(WK, Wh + DM * DM, Wl + DM * DM, DM * DM / 4);
    split_kernel<<<(DM * DM / 4 + NTH - 1) / NTH, NTH>>>(WV, Wh + 2 * DM * DM, Wl + 2 * DM * DM, DM * DM / 4);

    // 1) QKV projections (Q pre-scaled; V transposed)
    dim3 g1(DM / BN, NROWS / BM, 3);
    qkv_kernel<<<g1, NTH, SMEM_TOTAL>>>();

    // 2) causal scores (fp32) into attention output region
    dim3 g2(SEQ / BN, SEQ / BM, BSZ);
    scores_kernel<<<g2, NTH, SMEM_TOTAL>>>(att);

    // 3) softmax: fp32 probs to d_out, bf16 hi/lo probs to scratch
    softmax_kernel<<<NROWS, NTH>>>(att);

    // 4) O = P @ V + x
    dim3 g4(DM / BN, SEQ / BM, BSZ);
    av_kernel<<<g4, NTH, SMEM_TOTAL>>>(x, out);
}